// round 1
// baseline (speedup 1.0000x reference)
#include <cuda_runtime.h>

#define NWIRES  12
#define DIM     4096
#define NLAYERS 4
#define NT      256
#define PER     (DIM / NT)          // 16 elements per thread
#define NPAIRS  ((DIM / 2) / NT)    // 8 pairs per thread per gate pass

__device__ __forceinline__ float2 cmul(float2 a, float2 b) {
    return make_float2(fmaf(a.x, b.x, -(a.y * b.y)),
                       fmaf(a.x, b.y,   a.y * b.x));
}
__device__ __forceinline__ float2 cfma(float2 a, float2 b, float2 c) {
    // c += a*b (complex)
    c.x = fmaf(a.x, b.x, fmaf(-a.y, b.y, c.x));
    c.y = fmaf(a.x, b.y, fmaf( a.y, b.x, c.y));
    return c;
}

// logical -> physical index map after L applications of the CNOT-chain
// permutation g(j) = j ^ (j>>1)  (linear over GF(2), so g^k is cheap)
template <int L>
__device__ __forceinline__ int phi(int j) {
    if (L == 0) return j;
    if (L == 1) return j ^ (j >> 1);
    if (L == 2) return j ^ (j >> 2);
    if (L == 3) return j ^ (j >> 1) ^ (j >> 2) ^ (j >> 3);
    return j ^ (j >> 4);  // L == 4 (measurement)
}

template <int L>
__device__ __forceinline__ void do_layer(float2* st, const float2* Ug, int tid) {
    #pragma unroll
    for (int wi = 0; wi < NWIRES; ++wi) {
        const int base = (L * NWIRES + wi) * 4;
        const float2 u00 = Ug[base + 0];
        const float2 u01 = Ug[base + 1];
        const float2 u10 = Ug[base + 2];
        const float2 u11 = Ug[base + 3];
        const int p    = 11 - wi;           // wire wi lives on bit (11-wi)
        const int msk  = (1 << p) - 1;
        const int dphy = phi<L>(1 << p);    // physical offset of partner index
        #pragma unroll
        for (int it = 0; it < NPAIRS; ++it) {
            const int k  = tid + it * NT;
            const int i0 = ((k & ~msk) << 1) | (k & msk);
            const int q0 = phi<L>(i0);
            const int q1 = q0 ^ dphy;
            const float2 s0 = st[q0];
            const float2 s1 = st[q1];
            st[q0] = cfma(u01, s1, cmul(u00, s0));
            st[q1] = cfma(u11, s1, cmul(u10, s0));
        }
        __syncthreads();
    }
}

__global__ __launch_bounds__(NT)
void qnn_kernel(const float* __restrict__ x, const float* __restrict__ w,
                float* __restrict__ out)
{
    __shared__ float2 st[DIM];                      // 32 KB state
    __shared__ float2 Ug[NLAYERS * NWIRES * 4];     // fused per-(layer,wire) gates
    __shared__ float  red[8 * 8];                   // warp partials for reduction

    const int b   = blockIdx.x;
    const int tid = threadIdx.x;

    // ---- build fused gates: U = RZ(g) RY(b) RX(a) @ Enc  (48 threads) ----
    if (tid < NLAYERS * NWIRES) {
        const int l = tid / NWIRES, wi = tid % NWIRES;
        const float* wp = w + (l * NWIRES + wi) * 3;
        float sa, ca, sb, cb, sg, cg;
        sincosf(0.5f * wp[0], &sa, &ca);
        sincosf(0.5f * wp[1], &sb, &cb);
        sincosf(0.5f * wp[2], &sg, &cg);
        // RY*RX
        float2 m00 = make_float2( cb * ca,  sb * sa);
        float2 m01 = make_float2(-sb * ca, -cb * sa);
        float2 m10 = make_float2( sb * ca, -cb * sa);
        float2 m11 = make_float2( cb * ca, -sb * sa);
        // left-multiply RZ: row0 *= e^{-ig/2}, row1 *= e^{+ig/2}
        const float2 e0 = make_float2(cg, -sg);
        const float2 e1 = make_float2(cg,  sg);
        m00 = cmul(e0, m00); m01 = cmul(e0, m01);
        m10 = cmul(e1, m10); m11 = cmul(e1, m11);
        // encoding: even wire RX(x0), odd wire RY(x1)
        const float t = (wi & 1) ? x[b * 2 + 1] : x[b * 2 + 0];
        float se, ce;
        sincosf(0.5f * t, &se, &ce);
        float2 E00, E01, E10, E11;
        if (wi & 1) { // RY
            E00 = make_float2(ce, 0.f);  E01 = make_float2(-se, 0.f);
            E10 = make_float2(se, 0.f);  E11 = make_float2(ce, 0.f);
        } else {      // RX
            E00 = make_float2(ce, 0.f);  E01 = make_float2(0.f, -se);
            E10 = make_float2(0.f, -se); E11 = make_float2(ce, 0.f);
        }
        Ug[tid * 4 + 0] = cfma(m01, E10, cmul(m00, E00));
        Ug[tid * 4 + 1] = cfma(m01, E11, cmul(m00, E01));
        Ug[tid * 4 + 2] = cfma(m11, E10, cmul(m10, E00));
        Ug[tid * 4 + 3] = cfma(m11, E11, cmul(m10, E01));
    }
    __syncthreads();

    // ---- layer 0 applied to |0..0>: product state, written directly ----
    {
        // j = tid + lq*NT ; bits 0..7 of j = tid, bits 8..11 = lq
        float2 pt = make_float2(1.f, 0.f);
        #pragma unroll
        for (int bit = 0; bit < 8; ++bit) {
            const int wi = 11 - bit;                 // wire on bit `bit`
            pt = cmul(pt, Ug[wi * 4 + 2 * ((tid >> bit) & 1)]);  // column 0 of U
        }
        #pragma unroll
        for (int lq = 0; lq < PER; ++lq) {
            float2 v = pt;
            #pragma unroll
            for (int bit = 0; bit < 4; ++bit) {
                const int wi = 3 - bit;              // wire on bit (8+bit)
                v = cmul(v, Ug[wi * 4 + 2 * ((lq >> bit) & 1)]);
            }
            st[tid + lq * NT] = v;
        }
    }
    __syncthreads();

    // ---- layers 1..3 (CNOT chains absorbed into phi index remap) ----
    do_layer<1>(st, Ug, tid);
    do_layer<2>(st, Ug, tid);
    do_layer<3>(st, Ug, tid);

    // ---- measurement: logical j lives at phi<4>(j) ----
    float acc0 = 0.f, acc1 = 0.f, acc2 = 0.f, acc3 = 0.f, stot = 0.f;
    #pragma unroll
    for (int lq = 0; lq < PER; ++lq) {
        const int j = tid + lq * NT;
        const float2 v = st[phi<4>(j)];
        const float p = fmaf(v.x, v.x, v.y * v.y);
        stot += p;
        acc0 += ((lq >> 3) & 1) ? -p : p;   // wire 0 -> bit 11 -> lq bit 3
        acc1 += ((lq >> 2) & 1) ? -p : p;   // wire 1 -> bit 10
        acc2 += ((lq >> 1) & 1) ? -p : p;   // wire 2 -> bit 9
        acc3 += ((lq >> 0) & 1) ? -p : p;   // wire 3 -> bit 8
    }
    float r[8];
    r[0] = acc0; r[1] = acc1; r[2] = acc2; r[3] = acc3;
    r[4] = ((tid >> 7) & 1) ? -stot : stot;  // wire 4 -> bit 7 = tid bit 7
    r[5] = ((tid >> 6) & 1) ? -stot : stot;
    r[6] = ((tid >> 5) & 1) ? -stot : stot;
    r[7] = ((tid >> 4) & 1) ? -stot : stot;

    const unsigned FULL = 0xffffffffu;
    #pragma unroll
    for (int i = 0; i < 8; ++i) {
        float v = r[i];
        #pragma unroll
        for (int o = 16; o > 0; o >>= 1) v += __shfl_xor_sync(FULL, v, o);
        if ((tid & 31) == 0) red[(tid >> 5) * 8 + i] = v;
    }
    __syncthreads();
    if (tid < 8) {
        float s = 0.f;
        #pragma unroll
        for (int wp2 = 0; wp2 < 8; ++wp2) s += red[wp2 * 8 + tid];
        out[b * 8 + tid] = s * 3.14159265358979f;
    }
}

extern "C" void kernel_launch(void* const* d_in, const int* in_sizes, int n_in,
                              void* d_out, int out_size) {
    const float* x = (const float*)d_in[0];   // [B, 2]
    const float* w = (const float*)d_in[1];   // [4, 12, 3]
    float* out = (float*)d_out;               // [B, 8]
    const int B = in_sizes[0] / 2;
    qnn_kernel<<<B, NT>>>(x, w, out);
}

// round 2
// speedup vs baseline: 2.0856x; 2.0856x over previous
#include <cuda_runtime.h>

#define NWIRES  12
#define DIM     4096
#define NLAYERS 4
#define NT      256

__device__ __forceinline__ float2 cmul(float2 a, float2 b) {
    return make_float2(fmaf(a.x, b.x, -(a.y * b.y)),
                       fmaf(a.x, b.y,   a.y * b.x));
}
__device__ __forceinline__ float2 cfma(float2 a, float2 b, float2 c) {
    c.x = fmaf(a.x, b.x, fmaf(-a.y, b.y, c.x));
    c.y = fmaf(a.x, b.y, fmaf( a.y, b.x, c.y));
    return c;
}

// bank-conflict-avoiding swizzle: XOR low 4 bits with bits 4-7
__device__ __forceinline__ int saddr(int j) { return j ^ ((j >> 4) & 15); }

// h = g^{-1} where g(j)=j^(j>>1) is the CNOT-chain permutation (new[j]=old[g(j)]);
// h = prefix-XOR. Returns swizzled address of post-chain logical index.
__device__ __forceinline__ int haddr(int j) {
    j ^= j >> 1; j ^= j >> 2; j ^= j >> 4; j ^= j >> 8;
    return saddr(j);
}

// logical index owned by thread t, local slot v, for round R
// round R covers global bits [4R, 4R+3] (local bits) — those vary with v
template <int R>
__device__ __forceinline__ int jidx(int t, int v) {
    if (R == 0) return (t << 4) | v;
    if (R == 1) return ((t & 0xF0) << 4) | (v << 4) | (t & 15);
    return (v << 8) | t;
}

// gather 16 amplitudes and apply the 4 gates of this round in registers
template <int R>
__device__ __forceinline__ void gather_apply(const float2* __restrict__ st,
                                             const float2* __restrict__ Ul,
                                             int t, float2* r) {
    #pragma unroll
    for (int v = 0; v < 16; ++v) r[v] = st[saddr(jidx<R>(t, v))];
    #pragma unroll
    for (int lb = 0; lb < 4; ++lb) {
        const int wi = 11 - (4 * R + lb);   // wire living on global bit 4R+lb
        const float2 u00 = Ul[wi * 4 + 0];
        const float2 u01 = Ul[wi * 4 + 1];
        const float2 u10 = Ul[wi * 4 + 2];
        const float2 u11 = Ul[wi * 4 + 3];
        const int str = 1 << lb;
        #pragma unroll
        for (int p = 0; p < 8; ++p) {
            const int i0 = ((p & ~(str - 1)) << 1) | (p & (str - 1));
            const int i1 = i0 | str;
            const float2 s0 = r[i0], s1 = r[i1];
            r[i0] = cfma(u01, s1, cmul(u00, s0));
            r[i1] = cfma(u11, s1, cmul(u10, s0));
        }
    }
}

__global__ __launch_bounds__(NT, 2)
void qnn_kernel(const float* __restrict__ x, const float* __restrict__ w,
                float* __restrict__ out)
{
    __shared__ float2 st[DIM];                      // 32 KB state (swizzled layout)
    __shared__ float2 Ug[NLAYERS * NWIRES * 4];     // fused per-(layer,wire) gates
    __shared__ float  red[8 * 8];

    const int b   = blockIdx.x;
    const int t   = threadIdx.x;

    // ---- build fused gates: U = RZ RY RX @ Enc  (48 threads) ----
    if (t < NLAYERS * NWIRES) {
        const int l = t / NWIRES, wi = t % NWIRES;
        const float* wp = w + (l * NWIRES + wi) * 3;
        float sa, ca, sb, cb, sg, cg;
        sincosf(0.5f * wp[0], &sa, &ca);
        sincosf(0.5f * wp[1], &sb, &cb);
        sincosf(0.5f * wp[2], &sg, &cg);
        float2 m00 = make_float2( cb * ca,  sb * sa);
        float2 m01 = make_float2(-sb * ca, -cb * sa);
        float2 m10 = make_float2( sb * ca, -cb * sa);
        float2 m11 = make_float2( cb * ca, -sb * sa);
        const float2 e0 = make_float2(cg, -sg);
        const float2 e1 = make_float2(cg,  sg);
        m00 = cmul(e0, m00); m01 = cmul(e0, m01);
        m10 = cmul(e1, m10); m11 = cmul(e1, m11);
        const float th = (wi & 1) ? x[b * 2 + 1] : x[b * 2 + 0];
        float se, ce;
        sincosf(0.5f * th, &se, &ce);
        float2 E00, E01, E10, E11;
        if (wi & 1) { // RY
            E00 = make_float2(ce, 0.f);  E01 = make_float2(-se, 0.f);
            E10 = make_float2(se, 0.f);  E11 = make_float2(ce, 0.f);
        } else {      // RX
            E00 = make_float2(ce, 0.f);  E01 = make_float2(0.f, -se);
            E10 = make_float2(0.f, -se); E11 = make_float2(ce, 0.f);
        }
        Ug[t * 4 + 0] = cfma(m01, E10, cmul(m00, E00));
        Ug[t * 4 + 1] = cfma(m01, E11, cmul(m00, E01));
        Ug[t * 4 + 2] = cfma(m11, E10, cmul(m10, E00));
        Ug[t * 4 + 3] = cfma(m11, E11, cmul(m10, E01));
    }
    __syncthreads();

    // ---- layer 0 on |0..0>: product state, stored through CNOT-chain map h ----
    {
        float2 pt = make_float2(1.f, 0.f);
        #pragma unroll
        for (int bit = 0; bit < 8; ++bit)
            pt = cmul(pt, Ug[(11 - bit) * 4 + 2 * ((t >> bit) & 1)]);
        #pragma unroll
        for (int v = 0; v < 16; ++v) {
            float2 val = pt;
            #pragma unroll
            for (int bit = 0; bit < 4; ++bit)
                val = cmul(val, Ug[(3 - bit) * 4 + 2 * ((v >> bit) & 1)]);
            st[haddr((v << 8) | t)] = val;
        }
    }
    __syncthreads();

    float2 r[16];

    // ---- layers 1..2: 3 rounds each, last round stores through h ----
    for (int L = 1; L <= 2; ++L) {
        const float2* Ul = Ug + L * (NWIRES * 4);
        gather_apply<0>(st, Ul, t, r);
        #pragma unroll
        for (int v = 0; v < 16; ++v) st[saddr(jidx<0>(t, v))] = r[v];
        __syncthreads();
        gather_apply<1>(st, Ul, t, r);
        #pragma unroll
        for (int v = 0; v < 16; ++v) st[saddr(jidx<1>(t, v))] = r[v];
        __syncthreads();
        gather_apply<2>(st, Ul, t, r);
        #pragma unroll
        for (int v = 0; v < 16; ++v) st[haddr(jidx<2>(t, v))] = r[v];
        __syncthreads();
    }

    // ---- layer 3: rounds 0,1 as usual; round 2 fused with measurement ----
    {
        const float2* Ul = Ug + 3 * (NWIRES * 4);
        gather_apply<0>(st, Ul, t, r);
        #pragma unroll
        for (int v = 0; v < 16; ++v) st[saddr(jidx<0>(t, v))] = r[v];
        __syncthreads();
        gather_apply<1>(st, Ul, t, r);
        #pragma unroll
        for (int v = 0; v < 16; ++v) st[saddr(jidx<1>(t, v))] = r[v];
        __syncthreads();
        gather_apply<2>(st, Ul, t, r);
    }

    // ---- measurement straight from registers ----
    // register slot v of thread t holds pre-chain logical j=(v<<8)|t;
    // post-chain logical m = h(j); sign of wire i = bit (11-i) of m.
    // m bit (8+q) = XOR of v bits q..3 ; m bit k (k<8) = parity(v) ^ XOR of t bits k..7
    float acc0 = 0.f, acc1 = 0.f, acc2 = 0.f, se = 0.f, so = 0.f;
    #pragma unroll
    for (int v = 0; v < 16; ++v) {
        const float p = fmaf(r[v].x, r[v].x, r[v].y * r[v].y);
        const int b3 = (v >> 3) & 1, b2 = (v >> 2) & 1, b1 = (v >> 1) & 1, b0 = v & 1;
        acc0 += b3 ? -p : p;
        acc1 += (b3 ^ b2) ? -p : p;
        acc2 += (b3 ^ b2 ^ b1) ? -p : p;
        if (b3 ^ b2 ^ b1 ^ b0) so += p; else se += p;
    }
    const float d = se - so;   // = acc for wire 3, and |v|-parity difference
    const int t7 = (t >> 7) & 1, t6 = (t >> 6) & 1, t5 = (t >> 5) & 1, t4 = (t >> 4) & 1;
    float rr[8];
    rr[0] = acc0; rr[1] = acc1; rr[2] = acc2; rr[3] = d;
    rr[4] = t7 ? -d : d;
    rr[5] = (t7 ^ t6) ? -d : d;
    rr[6] = (t7 ^ t6 ^ t5) ? -d : d;
    rr[7] = (t7 ^ t6 ^ t5 ^ t4) ? -d : d;

    const unsigned FULL = 0xffffffffu;
    #pragma unroll
    for (int i = 0; i < 8; ++i) {
        float v = rr[i];
        #pragma unroll
        for (int o = 16; o > 0; o >>= 1) v += __shfl_xor_sync(FULL, v, o);
        if ((t & 31) == 0) red[(t >> 5) * 8 + i] = v;
    }
    __syncthreads();
    if (t < 8) {
        float s = 0.f;
        #pragma unroll
        for (int wp2 = 0; wp2 < 8; ++wp2) s += red[wp2 * 8 + t];
        out[b * 8 + t] = s * 3.14159265358979f;
    }
}

extern "C" void kernel_launch(void* const* d_in, const int* in_sizes, int n_in,
                              void* d_out, int out_size) {
    const float* x = (const float*)d_in[0];   // [B, 2]
    const float* w = (const float*)d_in[1];   // [4, 12, 3]
    float* out = (float*)d_out;               // [B, 8]
    const int B = in_sizes[0] / 2;
    qnn_kernel<<<B, NT>>>(x, w, out);
}

// round 3
// speedup vs baseline: 2.2157x; 1.0624x over previous
#include <cuda_runtime.h>

#define NWIRES  12
#define DIM     4096
#define NLAYERS 4
#define NT      256

typedef unsigned long long u64;

// ---- packed f32x2 helpers (Blackwell dual-fp32 pipe, PTX-only) ----
__device__ __forceinline__ u64 pk2(float lo, float hi) {
    u64 r; asm("mov.b64 %0, {%1,%2};" : "=l"(r) : "f"(lo), "f"(hi)); return r;
}
__device__ __forceinline__ void up2(u64 v, float& lo, float& hi) {
    asm("mov.b64 {%0,%1}, %2;" : "=f"(lo), "=f"(hi) : "l"(v));
}
__device__ __forceinline__ u64 swp(u64 v) {
    float a, b; up2(v, a, b); return pk2(b, a);
}
__device__ __forceinline__ u64 ffma2(u64 a, u64 b, u64 c) {
    u64 d; asm("fma.rn.f32x2 %0, %1, %2, %3;" : "=l"(d) : "l"(a), "l"(b), "l"(c)); return d;
}
__device__ __forceinline__ u64 fmul2(u64 a, u64 b) {
    u64 d; asm("mul.rn.f32x2 %0, %1, %2;" : "=l"(d) : "l"(a), "l"(b)); return d;
}

__device__ __forceinline__ float2 cmul(float2 a, float2 b) {
    return make_float2(fmaf(a.x, b.x, -(a.y * b.y)),
                       fmaf(a.x, b.y,   a.y * b.x));
}
__device__ __forceinline__ float2 cfma(float2 a, float2 b, float2 c) {
    c.x = fmaf(a.x, b.x, fmaf(-a.y, b.y, c.x));
    c.y = fmaf(a.x, b.y, fmaf( a.y, b.x, c.y));
    return c;
}

// bank-conflict-avoiding swizzle: XOR low 4 bits with bits 4-7
__device__ __forceinline__ int saddr(int j) { return j ^ ((j >> 4) & 15); }

// h = g^{-1} (prefix-XOR) of the CNOT-chain permutation, then swizzle
__device__ __forceinline__ int haddr(int j) {
    j ^= j >> 1; j ^= j >> 2; j ^= j >> 4; j ^= j >> 8;
    return saddr(j);
}

// logical index owned by thread t, local slot v, for round R
template <int R>
__device__ __forceinline__ int jidx(int t, int v) {
    if (R == 0) return (t << 4) | v;
    if (R == 1) return ((t & 0xF0) << 4) | (v << 4) | (t & 15);
    return (v << 8) | t;
}

// gather 16 amplitudes; apply the 4 gates of this round in registers (packed)
template <int R>
__device__ __forceinline__ void gather_apply(const u64* __restrict__ st,
                                             const u64* __restrict__ Ugp,
                                             int L, int t, u64* r) {
    #pragma unroll
    for (int v = 0; v < 16; ++v) r[v] = st[saddr(jidx<R>(t, v))];
    #pragma unroll
    for (int lb = 0; lb < 4; ++lb) {
        const int wi = 11 - (4 * R + lb);
        const u64* g = Ugp + (L * NWIRES + wi) * 8;
        const u64 cx00 = g[0], cy00 = g[1], cx01 = g[2], cy01 = g[3];
        const u64 cx10 = g[4], cy10 = g[5], cx11 = g[6], cy11 = g[7];
        const int str = 1 << lb;
        #pragma unroll
        for (int p = 0; p < 8; ++p) {
            const int i0 = ((p & ~(str - 1)) << 1) | (p & (str - 1));
            const int i1 = i0 | str;
            const u64 s0 = r[i0], s1 = r[i1];
            const u64 s0s = swp(s0), s1s = swp(s1);
            r[i0] = ffma2(cx00, s0, ffma2(cy00, s0s, ffma2(cx01, s1, fmul2(cy01, s1s))));
            r[i1] = ffma2(cx10, s0, ffma2(cy10, s0s, ffma2(cx11, s1, fmul2(cy11, s1s))));
        }
    }
}

__global__ __launch_bounds__(NT, 2)
void qnn_kernel(const float* __restrict__ x, const float* __restrict__ w,
                float* __restrict__ out)
{
    __shared__ u64 st[DIM];                          // 32 KB state (swizzled)
    __shared__ u64 Ugp[NLAYERS * NWIRES * 8];        // packed gate constants
    __shared__ float red[8 * 8];

    const int b = blockIdx.x;
    const int t = threadIdx.x;

    // ---- build fused gates U = RZ RY RX @ Enc, store packed (48 threads) ----
    if (t < NLAYERS * NWIRES) {
        const int l = t / NWIRES, wi = t % NWIRES;
        const float* wp = w + (l * NWIRES + wi) * 3;
        float sa, ca, sb, cb, sg, cg;
        sincosf(0.5f * wp[0], &sa, &ca);
        sincosf(0.5f * wp[1], &sb, &cb);
        sincosf(0.5f * wp[2], &sg, &cg);
        float2 m00 = make_float2( cb * ca,  sb * sa);
        float2 m01 = make_float2(-sb * ca, -cb * sa);
        float2 m10 = make_float2( sb * ca, -cb * sa);
        float2 m11 = make_float2( cb * ca, -sb * sa);
        const float2 e0 = make_float2(cg, -sg);
        const float2 e1 = make_float2(cg,  sg);
        m00 = cmul(e0, m00); m01 = cmul(e0, m01);
        m10 = cmul(e1, m10); m11 = cmul(e1, m11);
        const float th = (wi & 1) ? x[b * 2 + 1] : x[b * 2 + 0];
        float se, ce;
        sincosf(0.5f * th, &se, &ce);
        float2 E00, E01, E10, E11;
        if (wi & 1) { // RY
            E00 = make_float2(ce, 0.f);  E01 = make_float2(-se, 0.f);
            E10 = make_float2(se, 0.f);  E11 = make_float2(ce, 0.f);
        } else {      // RX
            E00 = make_float2(ce, 0.f);  E01 = make_float2(0.f, -se);
            E10 = make_float2(0.f, -se); E11 = make_float2(ce, 0.f);
        }
        const float2 u00 = cfma(m01, E10, cmul(m00, E00));
        const float2 u01 = cfma(m01, E11, cmul(m00, E01));
        const float2 u10 = cfma(m11, E10, cmul(m10, E00));
        const float2 u11 = cfma(m11, E11, cmul(m10, E01));
        u64* g = Ugp + t * 8;
        g[0] = pk2(u00.x, u00.x);  g[1] = pk2(-u00.y, u00.y);
        g[2] = pk2(u01.x, u01.x);  g[3] = pk2(-u01.y, u01.y);
        g[4] = pk2(u10.x, u10.x);  g[5] = pk2(-u10.y, u10.y);
        g[6] = pk2(u11.x, u11.x);  g[7] = pk2(-u11.y, u11.y);
    }
    __syncthreads();

    // ---- layer 0 on |0..0>: product state, stored through CNOT map h ----
    {
        u64 pt = pk2(1.f, 0.f);
        #pragma unroll
        for (int bit = 0; bit < 8; ++bit) {
            const u64* g = Ugp + (11 - bit) * 8;
            const int row = (t >> bit) & 1;          // column-0 entry, row = bit val
            pt = ffma2(g[4 * row], pt, fmul2(g[4 * row + 1], swp(pt)));
        }
        #pragma unroll
        for (int v = 0; v < 16; ++v) {
            u64 val = pt;
            #pragma unroll
            for (int bit = 0; bit < 4; ++bit) {
                const u64* g = Ugp + (3 - bit) * 8;
                const int row = (v >> bit) & 1;
                val = ffma2(g[4 * row], val, fmul2(g[4 * row + 1], swp(val)));
            }
            st[haddr((v << 8) | t)] = val;
        }
    }
    __syncthreads();

    u64 r[16];

    // ---- layers 1..2: 3 rounds each, last round scatters through h ----
    for (int L = 1; L <= 2; ++L) {
        gather_apply<0>(st, Ugp, L, t, r);
        #pragma unroll
        for (int v = 0; v < 16; ++v) st[saddr(jidx<0>(t, v))] = r[v];
        __syncthreads();
        gather_apply<1>(st, Ugp, L, t, r);
        #pragma unroll
        for (int v = 0; v < 16; ++v) st[saddr(jidx<1>(t, v))] = r[v];
        __syncthreads();
        gather_apply<2>(st, Ugp, L, t, r);
        #pragma unroll
        for (int v = 0; v < 16; ++v) st[haddr(jidx<2>(t, v))] = r[v];
        __syncthreads();
    }

    // ---- layer 3: rounds 0,1 as usual; round 2 fused with measurement ----
    {
        gather_apply<0>(st, Ugp, 3, t, r);
        #pragma unroll
        for (int v = 0; v < 16; ++v) st[saddr(jidx<0>(t, v))] = r[v];
        __syncthreads();
        gather_apply<1>(st, Ugp, 3, t, r);
        #pragma unroll
        for (int v = 0; v < 16; ++v) st[saddr(jidx<1>(t, v))] = r[v];
        __syncthreads();
        gather_apply<2>(st, Ugp, 3, t, r);
    }

    // ---- measurement straight from registers ----
    float acc0 = 0.f, acc1 = 0.f, acc2 = 0.f, se = 0.f, so = 0.f;
    #pragma unroll
    for (int v = 0; v < 16; ++v) {
        const u64 sq = fmul2(r[v], r[v]);
        float px, py; up2(sq, px, py);
        const float p = px + py;
        const int b3 = (v >> 3) & 1, b2 = (v >> 2) & 1, b1 = (v >> 1) & 1, b0 = v & 1;
        acc0 += b3 ? -p : p;
        acc1 += (b3 ^ b2) ? -p : p;
        acc2 += (b3 ^ b2 ^ b1) ? -p : p;
        if (b3 ^ b2 ^ b1 ^ b0) so += p; else se += p;
    }
    const float d = se - so;
    const int t7 = (t >> 7) & 1, t6 = (t >> 6) & 1, t5 = (t >> 5) & 1, t4 = (t >> 4) & 1;
    float rr[8];
    rr[0] = acc0; rr[1] = acc1; rr[2] = acc2; rr[3] = d;
    rr[4] = t7 ? -d : d;
    rr[5] = (t7 ^ t6) ? -d : d;
    rr[6] = (t7 ^ t6 ^ t5) ? -d : d;
    rr[7] = (t7 ^ t6 ^ t5 ^ t4) ? -d : d;

    const unsigned FULL = 0xffffffffu;
    #pragma unroll
    for (int i = 0; i < 8; ++i) {
        float v = rr[i];
        #pragma unroll
        for (int o = 16; o > 0; o >>= 1) v += __shfl_xor_sync(FULL, v, o);
        if ((t & 31) == 0) red[(t >> 5) * 8 + i] = v;
    }
    __syncthreads();
    if (t < 8) {
        float s = 0.f;
        #pragma unroll
        for (int wp2 = 0; wp2 < 8; ++wp2) s += red[wp2 * 8 + t];
        out[b * 8 + t] = s * 3.14159265358979f;
    }
}

extern "C" void kernel_launch(void* const* d_in, const int* in_sizes, int n_in,
                              void* d_out, int out_size) {
    const float* x = (const float*)d_in[0];   // [B, 2]
    const float* w = (const float*)d_in[1];   // [4, 12, 3]
    float* out = (float*)d_out;               // [B, 8]
    const int B = in_sizes[0] / 2;
    qnn_kernel<<<B, NT>>>(x, w, out);
}